// round 1
// baseline (speedup 1.0000x reference)
#include <cuda_runtime.h>
#include <cuda_bf16.h>
#include <math.h>

// Problem dims (fixed)
#define Dm   1024
#define Hh   16
#define DH   64
#define Rr   32
#define Bb   2
#define Ss   2048
#define BS   (Bb*Ss)        // 4096
#define HR   (Hh*Rr)        // 512
#define Ii   4096
#define RFC  512

// ---------------- scratch (device globals; no allocation allowed) ----------------
__device__ float g_x [BS*Dm];     // LN1 out, reused as LN2 out (z)
__device__ float g_Pq[BS*HR];
__device__ float g_Pk[BS*HR];
__device__ float g_Pv[BS*HR];
__device__ float g_Q [Bb*Hh*Ss*DH];
__device__ float g_K [Bb*Hh*Ss*DH];
__device__ float g_V [Bb*Hh*Ss*DH];
__device__ float g_Y [BS*Dm];     // attention out in (b,s,h,e)
__device__ float g_t [BS*RFC];    // low-rank intermediates (reused 3x)
__device__ float g_h [BS*Dm];     // residual stream after attn
__device__ float g_a [BS*Ii];     // MLP hidden

// ---------------- LayerNorm ----------------
__global__ void ln_kernel(const float* __restrict__ in, const float* __restrict__ w,
                          const float* __restrict__ b, float* __restrict__ out) {
    __shared__ float xs[Dm];
    __shared__ float red[8];
    int row = blockIdx.x;
    int t = threadIdx.x;                 // 256 threads
    const float* x = in + (size_t)row * Dm;

    float s = 0.f;
    #pragma unroll
    for (int i = t; i < Dm; i += 256) { float v = x[i]; xs[i] = v; s += v; }
    #pragma unroll
    for (int o = 16; o; o >>= 1) s += __shfl_xor_sync(0xffffffffu, s, o);
    if ((t & 31) == 0) red[t >> 5] = s;
    __syncthreads();
    float tot = 0.f;
    #pragma unroll
    for (int i = 0; i < 8; i++) tot += red[i];
    float mean = tot * (1.0f / Dm);
    __syncthreads();

    float vs = 0.f;
    #pragma unroll
    for (int i = t; i < Dm; i += 256) { float d = xs[i] - mean; vs += d * d; }
    #pragma unroll
    for (int o = 16; o; o >>= 1) vs += __shfl_xor_sync(0xffffffffu, vs, o);
    if ((t & 31) == 0) red[t >> 5] = vs;
    __syncthreads();
    float vtot = 0.f;
    #pragma unroll
    for (int i = 0; i < 8; i++) vtot += red[i];
    float rstd = rsqrtf(vtot * (1.0f / Dm) + 1e-5f);

    #pragma unroll
    for (int i = t; i < Dm; i += 256)
        out[(size_t)row * Dm + i] = (xs[i] - mean) * rstd * w[i] + b[i];
}

// ---------------- generic fp32 SGEMM 128x128x8, epilogue fused ----------------
// EPI: 0 = C = A*B
//      1 = C = A*B + bias[col] + res[row,col]
//      2 = C = gelu_tanh(A*B + bias[col])
__device__ __forceinline__ float gelu_tanh(float x) {
    float x3 = x * x * x;
    return 0.5f * x * (1.f + tanhf(0.7978845608f * (x + 0.044715f * x3)));
}

template<int EPI>
__global__ void sgemm128(const float* __restrict__ A, const float* __restrict__ B,
                         float* __restrict__ C, int M, int N, int K,
                         const float* __restrict__ bias, const float* __restrict__ res) {
    __shared__ float As[8][128];
    __shared__ float Bs[8][128];
    int tid = threadIdx.x;               // 256
    int m0 = blockIdx.y * 128, n0 = blockIdx.x * 128;
    int tx = tid & 15, ty = tid >> 4;    // 16x16

    float acc[8][8];
    #pragma unroll
    for (int i = 0; i < 8; i++)
        #pragma unroll
        for (int j = 0; j < 8; j++) acc[i][j] = 0.f;

    int arow = tid >> 1;                 // 0..127
    int acol = (tid & 1) * 4;            // 0 or 4
    int brow = tid >> 5;                 // 0..7
    int bcol = (tid & 31) * 4;           // 0..124
    const float* Aptr = A + (size_t)(m0 + arow) * K + acol;
    const float* Bptr = B + (size_t)brow * N + n0 + bcol;

    for (int k0 = 0; k0 < K; k0 += 8) {
        float4 av = *(const float4*)Aptr;
        As[acol + 0][arow] = av.x;
        As[acol + 1][arow] = av.y;
        As[acol + 2][arow] = av.z;
        As[acol + 3][arow] = av.w;
        *(float4*)(&Bs[brow][bcol]) = *(const float4*)Bptr;
        __syncthreads();

        #pragma unroll
        for (int kk = 0; kk < 8; kk++) {
            float4 a0 = *(const float4*)(&As[kk][ty * 8]);
            float4 a1 = *(const float4*)(&As[kk][ty * 8 + 4]);
            float4 b0 = *(const float4*)(&Bs[kk][tx * 8]);
            float4 b1 = *(const float4*)(&Bs[kk][tx * 8 + 4]);
            float a[8] = {a0.x, a0.y, a0.z, a0.w, a1.x, a1.y, a1.z, a1.w};
            float b[8] = {b0.x, b0.y, b0.z, b0.w, b1.x, b1.y, b1.z, b1.w};
            #pragma unroll
            for (int i = 0; i < 8; i++)
                #pragma unroll
                for (int j = 0; j < 8; j++) acc[i][j] = fmaf(a[i], b[j], acc[i][j]);
        }
        __syncthreads();
        Aptr += 8;
        Bptr += (size_t)8 * N;
    }

    #pragma unroll
    for (int i = 0; i < 8; i++) {
        int row = m0 + ty * 8 + i;
        float* crow = C + (size_t)row * N + n0 + tx * 8;
        const float* rrow = (EPI == 1) ? (res + (size_t)row * N + n0 + tx * 8) : nullptr;
        #pragma unroll
        for (int j = 0; j < 8; j++) {
            float v = acc[i][j];
            if (EPI == 1) v += bias[n0 + tx * 8 + j] + rrow[j];
            if (EPI == 2) v = gelu_tanh(v + bias[n0 + tx * 8 + j]);
            crow[j] = v;
        }
    }
}

// ---------------- per-head rank-32 projection: out[b,h,s,e] = P[bs, h*32+r] @ Vw[h,r,e] + b[h,e]
__global__ void head_proj(const float* __restrict__ P, const float* __restrict__ Vw,
                          const float* __restrict__ bias, float* __restrict__ out) {
    __shared__ float p[Rr];
    int bs = blockIdx.x;                 // 0..4095
    int h = blockIdx.y;                  // 0..15
    int e = threadIdx.x;                 // 0..63
    if (e < Rr) p[e] = P[(size_t)bs * HR + h * Rr + e];
    __syncthreads();
    float acc = bias[h * DH + e];
    const float* vw = Vw + (size_t)h * Rr * DH + e;
    #pragma unroll
    for (int r = 0; r < Rr; r++) acc = fmaf(p[r], vw[r * DH], acc);
    int b = bs >> 11, s = bs & 2047;
    out[(((size_t)(b * Hh + h)) * Ss + s) * DH + e] = acc;
}

// ---------------- causal flash attention, 64 queries / block ----------------
__global__ void attn_kernel(const float* __restrict__ Q, const float* __restrict__ K,
                            const float* __restrict__ V, float* __restrict__ Y) {
    __shared__ float Ks[64 * 64];
    __shared__ float Vs[64 * 64];
    __shared__ float Sc[64 * 64];        // [j][lane]
    int bh = blockIdx.y;
    int qblk = gridDim.x - 1 - blockIdx.x;   // heavy (long-context) blocks first
    int t = threadIdx.x;                 // 0..63
    int q = qblk * 64 + t;

    const float* qptr = Q + ((size_t)bh * Ss + q) * DH;
    float qr[DH];
    #pragma unroll
    for (int e = 0; e < DH; e += 4) {
        float4 v = *(const float4*)(qptr + e);
        qr[e] = v.x; qr[e + 1] = v.y; qr[e + 2] = v.z; qr[e + 3] = v.w;
    }
    float acc[DH];
    #pragma unroll
    for (int e = 0; e < DH; e++) acc[e] = 0.f;
    float m = -1e30f, l = 0.f;
    const float scale = 0.125f;          // 1/sqrt(64)

    for (int kt = 0; kt <= qblk; kt++) {
        const float* kbase = K + ((size_t)bh * Ss + kt * 64) * DH;
        const float* vbase = V + ((size_t)bh * Ss + kt * 64) * DH;
        __syncthreads();
        #pragma unroll
        for (int i = 0; i < 16; i++) {
            int idx = (i * 64 + t) * 4;
            *(float4*)(Ks + idx) = *(const float4*)(kbase + idx);
            *(float4*)(Vs + idx) = *(const float4*)(vbase + idx);
        }
        __syncthreads();

        int jmax = min(64, q - kt * 64 + 1);   // causal bound
        float tm = -1e30f;
        for (int j = 0; j < jmax; j++) {
            float s = 0.f;
            #pragma unroll
            for (int e = 0; e < DH; e++) s = fmaf(qr[e], Ks[j * 64 + e], s);
            s *= scale;
            Sc[j * 64 + t] = s;
            tm = fmaxf(tm, s);
        }
        float mnew = fmaxf(m, tm);
        float corr = __expf(m - mnew);
        l *= corr;
        #pragma unroll
        for (int e = 0; e < DH; e++) acc[e] *= corr;
        for (int j = 0; j < jmax; j++) {
            float p = __expf(Sc[j * 64 + t] - mnew);
            l += p;
            #pragma unroll
            for (int e = 0; e < DH; e++) acc[e] = fmaf(p, Vs[j * 64 + e], acc[e]);
        }
        m = mnew;
    }

    int b = bh >> 4, h = bh & 15;
    float inv = 1.f / l;
    float* yptr = Y + (((size_t)(b * Ss + q)) * Hh + h) * DH;  // (b,s,h,e)
    #pragma unroll
    for (int e = 0; e < DH; e++) yptr[e] = acc[e] * inv;
}

// ---------------- launch ----------------
extern "C" void kernel_launch(void* const* d_in, const int* in_sizes, int n_in,
                              void* d_out, int out_size) {
    const float* hidden = (const float*)d_in[0];
    // d_in[1] = attention_mask (all true; causal-only is exact)
    const float* ln1_w = (const float*)d_in[2];
    const float* ln1_b = (const float*)d_in[3];
    const float* q_U = (const float*)d_in[4];
    const float* q_V = (const float*)d_in[5];
    const float* q_b = (const float*)d_in[6];
    const float* k_U = (const float*)d_in[7];
    const float* k_V = (const float*)d_in[8];
    const float* k_b = (const float*)d_in[9];
    const float* v_U = (const float*)d_in[10];
    const float* v_V = (const float*)d_in[11];
    const float* v_b = (const float*)d_in[12];
    const float* out_U = (const float*)d_in[13];
    const float* out_V = (const float*)d_in[14];
    const float* out_b = (const float*)d_in[15];
    const float* ln2_w = (const float*)d_in[16];
    const float* ln2_b = (const float*)d_in[17];
    const float* fc1_U = (const float*)d_in[18];
    const float* fc1_V = (const float*)d_in[19];
    const float* fc1_b = (const float*)d_in[20];
    const float* fc2_U = (const float*)d_in[21];
    const float* fc2_V = (const float*)d_in[22];
    const float* fc2_b = (const float*)d_in[23];
    float* out = (float*)d_out;

    float *x_, *Pq_, *Pk_, *Pv_, *Q_, *K_, *V_, *Y_, *t_, *h_, *a_;
    cudaGetSymbolAddress((void**)&x_,  g_x);
    cudaGetSymbolAddress((void**)&Pq_, g_Pq);
    cudaGetSymbolAddress((void**)&Pk_, g_Pk);
    cudaGetSymbolAddress((void**)&Pv_, g_Pv);
    cudaGetSymbolAddress((void**)&Q_,  g_Q);
    cudaGetSymbolAddress((void**)&K_,  g_K);
    cudaGetSymbolAddress((void**)&V_,  g_V);
    cudaGetSymbolAddress((void**)&Y_,  g_Y);
    cudaGetSymbolAddress((void**)&t_,  g_t);
    cudaGetSymbolAddress((void**)&h_,  g_h);
    cudaGetSymbolAddress((void**)&a_,  g_a);

    // 1) x = LN1(hidden)
    ln_kernel<<<BS, 256>>>(hidden, ln1_w, ln1_b, x_);

    // 2) Pq/Pk/Pv = x @ {q,k,v}_U   (4096x1024 @ 1024x512)
    {
        dim3 g(HR / 128, BS / 128);
        sgemm128<0><<<g, 256>>>(x_, q_U, Pq_, BS, HR, Dm, nullptr, nullptr);
        sgemm128<0><<<g, 256>>>(x_, k_U, Pk_, BS, HR, Dm, nullptr, nullptr);
        sgemm128<0><<<g, 256>>>(x_, v_U, Pv_, BS, HR, Dm, nullptr, nullptr);
    }

    // 3) per-head rank-32 expansion -> Q,K,V in (b,h,s,e)
    {
        dim3 g(BS, Hh);
        head_proj<<<g, 64>>>(Pq_, q_V, q_b, Q_);
        head_proj<<<g, 64>>>(Pk_, k_V, k_b, K_);
        head_proj<<<g, 64>>>(Pv_, v_V, v_b, V_);
    }

    // 4) causal attention -> Y (b,s,h,e) == (4096, 1024)
    {
        dim3 g(Ss / 64, Bb * Hh);
        attn_kernel<<<g, 64>>>(Q_, K_, V_, Y_);
    }

    // 5) out proj low-rank + residual: h = hidden + (Y @ out_U) @ out_V + out_b
    {
        dim3 g1(RFC / 128, BS / 128);
        sgemm128<0><<<g1, 256>>>(Y_, out_U, t_, BS, RFC, Dm, nullptr, nullptr);
        dim3 g2(Dm / 128, BS / 128);
        sgemm128<1><<<g2, 256>>>(t_, out_V, h_, BS, Dm, RFC, out_b, hidden);
    }

    // 6) z = LN2(h)  (into g_x, reuse)
    ln_kernel<<<BS, 256>>>(h_, ln2_w, ln2_b, x_);

    // 7) MLP: a = gelu((z @ fc1_U) @ fc1_V + fc1_b)
    {
        dim3 g1(RFC / 128, BS / 128);
        sgemm128<0><<<g1, 256>>>(x_, fc1_U, t_, BS, RFC, Dm, nullptr, nullptr);
        dim3 g2(Ii / 128, BS / 128);
        sgemm128<2><<<g2, 256>>>(t_, fc1_V, a_, BS, Ii, RFC, fc1_b, nullptr);
    }

    // 8) out = h + (a @ fc2_U) @ fc2_V + fc2_b
    {
        dim3 g1(RFC / 128, BS / 128);
        sgemm128<0><<<g1, 256>>>(a_, fc2_U, t_, BS, RFC, Ii, nullptr, nullptr);
        dim3 g2(Dm / 128, BS / 128);
        sgemm128<1><<<g2, 256>>>(t_, fc2_V, out, BS, Dm, RFC, fc2_b, h_);
    }
}

// round 2
// speedup vs baseline: 1.8892x; 1.8892x over previous
#include <cuda_runtime.h>
#include <cuda_bf16.h>
#include <math.h>
#include <stdint.h>

// Problem dims (fixed)
#define Dm   1024
#define Hh   16
#define DH   64
#define Rr   32
#define Bb   2
#define Ss   2048
#define BS   (Bb*Ss)        // 4096
#define HR   (Hh*Rr)        // 512
#define Ii   4096
#define RFC  512

// ---------------- scratch (device globals; no allocation allowed) ----------------
__device__ float g_x [BS*Dm];
__device__ float g_Pq[BS*HR];
__device__ float g_Pk[BS*HR];
__device__ float g_Pv[BS*HR];
__device__ float g_Q [Bb*Hh*Ss*DH];
__device__ float g_K [Bb*Hh*Ss*DH];
__device__ float g_V [Bb*Hh*Ss*DH];
__device__ float g_Y [BS*Dm];
__device__ float g_t [BS*RFC];
__device__ float g_h [BS*Dm];
__device__ float g_a [BS*Ii];

// ---------------- LayerNorm ----------------
__global__ void ln_kernel(const float* __restrict__ in, const float* __restrict__ w,
                          const float* __restrict__ b, float* __restrict__ out) {
    __shared__ float xs[Dm];
    __shared__ float red[8];
    int row = blockIdx.x;
    int t = threadIdx.x;
    const float* x = in + (size_t)row * Dm;

    float s = 0.f;
    #pragma unroll
    for (int i = t; i < Dm; i += 256) { float v = x[i]; xs[i] = v; s += v; }
    #pragma unroll
    for (int o = 16; o; o >>= 1) s += __shfl_xor_sync(0xffffffffu, s, o);
    if ((t & 31) == 0) red[t >> 5] = s;
    __syncthreads();
    float tot = 0.f;
    #pragma unroll
    for (int i = 0; i < 8; i++) tot += red[i];
    float mean = tot * (1.0f / Dm);
    __syncthreads();

    float vs = 0.f;
    #pragma unroll
    for (int i = t; i < Dm; i += 256) { float d = xs[i] - mean; vs += d * d; }
    #pragma unroll
    for (int o = 16; o; o >>= 1) vs += __shfl_xor_sync(0xffffffffu, vs, o);
    if ((t & 31) == 0) red[t >> 5] = vs;
    __syncthreads();
    float vtot = 0.f;
    #pragma unroll
    for (int i = 0; i < 8; i++) vtot += red[i];
    float rstd = rsqrtf(vtot * (1.0f / Dm) + 1e-5f);

    #pragma unroll
    for (int i = t; i < Dm; i += 256)
        out[(size_t)row * Dm + i] = (xs[i] - mean) * rstd * w[i] + b[i];
}

// ---------------- TF32 tensor-core GEMM ----------------
__device__ __forceinline__ float gelu_tanh(float x) {
    float x3 = x * x * x;
    return 0.5f * x * (1.f + tanhf(0.7978845608f * (x + 0.044715f * x3)));
}

__device__ __forceinline__ void cp16(uint32_t saddr, const void* gptr) {
    asm volatile("cp.async.ca.shared.global [%0], [%1], 16;" :: "r"(saddr), "l"(gptr));
}
__device__ __forceinline__ uint32_t f2tf(float x) {
    uint32_t r;
    asm("cvt.rna.tf32.f32 %0, %1;" : "=r"(r) : "f"(x));
    return r;
}
__device__ __forceinline__ void mma_tf32(float* d, const uint32_t* a, const uint32_t* b) {
    asm volatile(
        "mma.sync.aligned.m16n8k8.row.col.f32.tf32.tf32.f32 "
        "{%0,%1,%2,%3}, {%4,%5,%6,%7}, {%8,%9}, {%0,%1,%2,%3};"
        : "+f"(d[0]), "+f"(d[1]), "+f"(d[2]), "+f"(d[3])
        : "r"(a[0]), "r"(a[1]), "r"(a[2]), "r"(a[3]), "r"(b[0]), "r"(b[1]));
}

// EPI: 0 = C=A*B ; 1 = C=A*B+bias[col]+res[row,col] ; 2 = C=gelu(A*B+bias[col])
template<int EPI, int BN>
__device__ __forceinline__ void gemm_core(
    const float* __restrict__ A, const float* __restrict__ B, float* __restrict__ C,
    int M, int N, int K, const float* __restrict__ bias, const float* __restrict__ res,
    int m0, int n0)
{
    constexpr int BM = 128, BK = 16;
    constexpr int WM_ = (BN == 128) ? 2 : 4;   // warps along m
    constexpr int WTM = BM / WM_;              // 64 or 32
    constexpr int WTN = BN / (8 / WM_);        // 32
    constexpr int MT = WTM / 16;               // 4 or 2
    constexpr int NT = WTN / 8;                // 4

    __shared__ __align__(16) float As[2][BM][BK + 4];   // stride 20 -> conflict-free frag lds
    __shared__ __align__(16) float Bs[2][BK][BN + 8];   // stride BN+8 -> conflict-free frag lds

    int tid = threadIdx.x;
    int w = tid >> 5, lane = tid & 31;
    int lr = lane >> 2, lc = lane & 3;
    int wm = (w % WM_) * WTM;
    int wn = (w / WM_) * WTN;

    float acc[MT][NT][4];
    #pragma unroll
    for (int mt = 0; mt < MT; mt++)
        #pragma unroll
        for (int nt = 0; nt < NT; nt++)
            #pragma unroll
            for (int i = 0; i < 4; i++) acc[mt][nt][i] = 0.f;

    const float* Ag = A + (size_t)m0 * K;
    const float* Bg = B + n0;

    auto loadTile = [&](int kt, int buf) {
        int k0 = kt * BK;
        #pragma unroll
        for (int i = 0; i < 2; i++) {           // A: 512 x 16B chunks
            int q = tid * 2 + i;
            int m = q >> 2, c = q & 3;
            uint32_t s = (uint32_t)__cvta_generic_to_shared(&As[buf][m][c * 4]);
            cp16(s, Ag + (size_t)m * K + k0 + c * 4);
        }
        #pragma unroll
        for (int i = 0; i < BN / 64; i++) {     // B: 4*BN x 16B chunks
            int q = tid + i * 256;
            int k = q / (BN / 4), n4 = q % (BN / 4);
            uint32_t s = (uint32_t)__cvta_generic_to_shared(&Bs[buf][k][n4 * 4]);
            cp16(s, Bg + (size_t)(k0 + k) * N + n4 * 4);
        }
        asm volatile("cp.async.commit_group;");
    };

    int NTILES = K / BK;
    loadTile(0, 0);
    for (int kt = 0; kt < NTILES; kt++) {
        int buf = kt & 1;
        if (kt + 1 < NTILES) {
            loadTile(kt + 1, buf ^ 1);
            asm volatile("cp.async.wait_group 1;");
        } else {
            asm volatile("cp.async.wait_group 0;");
        }
        __syncthreads();

        #pragma unroll
        for (int ks = 0; ks < 2; ks++) {
            int kb = ks * 8;
            uint32_t af[MT][4], bf[NT][2];
            #pragma unroll
            for (int mt = 0; mt < MT; mt++) {
                int r = wm + mt * 16 + lr;
                af[mt][0] = f2tf(As[buf][r][kb + lc]);
                af[mt][1] = f2tf(As[buf][r + 8][kb + lc]);
                af[mt][2] = f2tf(As[buf][r][kb + lc + 4]);
                af[mt][3] = f2tf(As[buf][r + 8][kb + lc + 4]);
            }
            #pragma unroll
            for (int nt = 0; nt < NT; nt++) {
                int cn = wn + nt * 8 + lr;
                bf[nt][0] = f2tf(Bs[buf][kb + lc][cn]);
                bf[nt][1] = f2tf(Bs[buf][kb + lc + 4][cn]);
            }
            #pragma unroll
            for (int mt = 0; mt < MT; mt++)
                #pragma unroll
                for (int nt = 0; nt < NT; nt++)
                    mma_tf32(acc[mt][nt], af[mt], bf[nt]);
        }
        __syncthreads();
    }

    // epilogue
    #pragma unroll
    for (int mt = 0; mt < MT; mt++) {
        #pragma unroll
        for (int h = 0; h < 2; h++) {
            int row = m0 + wm + mt * 16 + lr + h * 8;
            #pragma unroll
            for (int nt = 0; nt < NT; nt++) {
                int col = n0 + wn + nt * 8 + 2 * lc;
                float v0 = acc[mt][nt][2 * h + 0];
                float v1 = acc[mt][nt][2 * h + 1];
                if (EPI == 1) {
                    v0 += bias[col]     + res[(size_t)row * N + col];
                    v1 += bias[col + 1] + res[(size_t)row * N + col + 1];
                } else if (EPI == 2) {
                    v0 = gelu_tanh(v0 + bias[col]);
                    v1 = gelu_tanh(v1 + bias[col + 1]);
                }
                *(float2*)&C[(size_t)row * N + col] = make_float2(v0, v1);
            }
        }
    }
}

template<int EPI, int BN>
__global__ void __launch_bounds__(256, 2) sgemm_t(
    const float* __restrict__ A, const float* __restrict__ B, float* __restrict__ C,
    int M, int N, int K, const float* __restrict__ bias, const float* __restrict__ res)
{
    gemm_core<EPI, BN>(A, B, C, M, N, K, bias, res, blockIdx.y * 128, blockIdx.x * BN);
}

// fused Pq/Pk/Pv: 3 matrices x 4 column-blocks on blockIdx.x
__global__ void __launch_bounds__(256, 2) sgemm_qkv(
    const float* __restrict__ A,
    const float* __restrict__ B0, const float* __restrict__ B1, const float* __restrict__ B2,
    float* __restrict__ C0, float* __restrict__ C1, float* __restrict__ C2,
    int M, int N, int K)
{
    int sel = blockIdx.x >> 2, nb = blockIdx.x & 3;
    const float* B = (sel == 0) ? B0 : (sel == 1) ? B1 : B2;
    float* C = (sel == 0) ? C0 : (sel == 1) ? C1 : C2;
    gemm_core<0, 128>(A, B, C, M, N, K, nullptr, nullptr, blockIdx.y * 128, nb * 128);
}

// ---------------- per-head rank-32 projection ----------------
__global__ void head_proj(const float* __restrict__ P, const float* __restrict__ Vw,
                          const float* __restrict__ bias, float* __restrict__ out) {
    __shared__ float p[Rr];
    int bs = blockIdx.x;
    int h = blockIdx.y;
    int e = threadIdx.x;
    if (e < Rr) p[e] = P[(size_t)bs * HR + h * Rr + e];
    __syncthreads();
    float acc = bias[h * DH + e];
    const float* vw = Vw + (size_t)h * Rr * DH + e;
    #pragma unroll
    for (int r = 0; r < Rr; r++) acc = fmaf(p[r], vw[r * DH], acc);
    int b = bs >> 11, s = bs & 2047;
    out[(((size_t)(b * Hh + h)) * Ss + s) * DH + e] = acc;
}

// ---------------- causal flash attention, 64 queries / block ----------------
__global__ void attn_kernel(const float* __restrict__ Q, const float* __restrict__ K,
                            const float* __restrict__ V, float* __restrict__ Y) {
    __shared__ float Ks[64 * 64];
    __shared__ float Vs[64 * 64];
    __shared__ float Sc[64 * 64];
    int bh = blockIdx.y;
    int qblk = gridDim.x - 1 - blockIdx.x;
    int t = threadIdx.x;
    int q = qblk * 64 + t;

    const float* qptr = Q + ((size_t)bh * Ss + q) * DH;
    float qr[DH];
    #pragma unroll
    for (int e = 0; e < DH; e += 4) {
        float4 v = *(const float4*)(qptr + e);
        qr[e] = v.x; qr[e + 1] = v.y; qr[e + 2] = v.z; qr[e + 3] = v.w;
    }
    float acc[DH];
    #pragma unroll
    for (int e = 0; e < DH; e++) acc[e] = 0.f;
    float m = -1e30f, l = 0.f;
    const float scale = 0.125f;

    for (int kt = 0; kt <= qblk; kt++) {
        const float* kbase = K + ((size_t)bh * Ss + kt * 64) * DH;
        const float* vbase = V + ((size_t)bh * Ss + kt * 64) * DH;
        __syncthreads();
        #pragma unroll
        for (int i = 0; i < 16; i++) {
            int idx = (i * 64 + t) * 4;
            *(float4*)(Ks + idx) = *(const float4*)(kbase + idx);
            *(float4*)(Vs + idx) = *(const float4*)(vbase + idx);
        }
        __syncthreads();

        int jmax = min(64, q - kt * 64 + 1);
        float tm = -1e30f;
        for (int j = 0; j < jmax; j++) {
            float s = 0.f;
            #pragma unroll
            for (int e = 0; e < DH; e++) s = fmaf(qr[e], Ks[j * 64 + e], s);
            s *= scale;
            Sc[j * 64 + t] = s;
            tm = fmaxf(tm, s);
        }
        float mnew = fmaxf(m, tm);
        float corr = __expf(m - mnew);
        l *= corr;
        #pragma unroll
        for (int e = 0; e < DH; e++) acc[e] *= corr;
        for (int j = 0; j < jmax; j++) {
            float p = __expf(Sc[j * 64 + t] - mnew);
            l += p;
            #pragma unroll
            for (int e = 0; e < DH; e++) acc[e] = fmaf(p, Vs[j * 64 + e], acc[e]);
        }
        m = mnew;
    }

    int b = bh >> 4, h = bh & 15;
    float inv = 1.f / l;
    float* yptr = Y + (((size_t)(b * Ss + q)) * Hh + h) * DH;
    #pragma unroll
    for (int e = 0; e < DH; e++) yptr[e] = acc[e] * inv;
}

// ---------------- launch ----------------
extern "C" void kernel_launch(void* const* d_in, const int* in_sizes, int n_in,
                              void* d_out, int out_size) {
    const float* hidden = (const float*)d_in[0];
    const float* ln1_w = (const float*)d_in[2];
    const float* ln1_b = (const float*)d_in[3];
    const float* q_U = (const float*)d_in[4];
    const float* q_V = (const float*)d_in[5];
    const float* q_b = (const float*)d_in[6];
    const float* k_U = (const float*)d_in[7];
    const float* k_V = (const float*)d_in[8];
    const float* k_b = (const float*)d_in[9];
    const float* v_U = (const float*)d_in[10];
    const float* v_V = (const float*)d_in[11];
    const float* v_b = (const float*)d_in[12];
    const float* out_U = (const float*)d_in[13];
    const float* out_V = (const float*)d_in[14];
    const float* out_b = (const float*)d_in[15];
    const float* ln2_w = (const float*)d_in[16];
    const float* ln2_b = (const float*)d_in[17];
    const float* fc1_U = (const float*)d_in[18];
    const float* fc1_V = (const float*)d_in[19];
    const float* fc1_b = (const float*)d_in[20];
    const float* fc2_U = (const float*)d_in[21];
    const float* fc2_V = (const float*)d_in[22];
    const float* fc2_b = (const float*)d_in[23];
    float* out = (float*)d_out;

    float *x_, *Pq_, *Pk_, *Pv_, *Q_, *K_, *V_, *Y_, *t_, *h_, *a_;
    cudaGetSymbolAddress((void**)&x_,  g_x);
    cudaGetSymbolAddress((void**)&Pq_, g_Pq);
    cudaGetSymbolAddress((void**)&Pk_, g_Pk);
    cudaGetSymbolAddress((void**)&Pv_, g_Pv);
    cudaGetSymbolAddress((void**)&Q_,  g_Q);
    cudaGetSymbolAddress((void**)&K_,  g_K);
    cudaGetSymbolAddress((void**)&V_,  g_V);
    cudaGetSymbolAddress((void**)&Y_,  g_Y);
    cudaGetSymbolAddress((void**)&t_,  g_t);
    cudaGetSymbolAddress((void**)&h_,  g_h);
    cudaGetSymbolAddress((void**)&a_,  g_a);

    // 1) x = LN1(hidden)
    ln_kernel<<<BS, 256>>>(hidden, ln1_w, ln1_b, x_);

    // 2) Pq/Pk/Pv = x @ {q,k,v}_U  — single fused launch (384 CTAs)
    {
        dim3 g(12, BS / 128);
        sgemm_qkv<<<g, 256>>>(x_, q_U, k_U, v_U, Pq_, Pk_, Pv_, BS, HR, Dm);
    }

    // 3) per-head rank-32 expansion -> Q,K,V (b,h,s,e)
    {
        dim3 g(BS, Hh);
        head_proj<<<g, 64>>>(Pq_, q_V, q_b, Q_);
        head_proj<<<g, 64>>>(Pk_, k_V, k_b, K_);
        head_proj<<<g, 64>>>(Pv_, v_V, v_b, V_);
    }

    // 4) causal attention -> Y (b,s,h,e)
    {
        dim3 g(Ss / 64, Bb * Hh);
        attn_kernel<<<g, 64>>>(Q_, K_, V_, Y_);
    }

    // 5) h = hidden + (Y @ out_U) @ out_V + out_b
    {
        dim3 g1(RFC / 64, BS / 128);
        sgemm_t<0, 64><<<g1, 256>>>(Y_, out_U, t_, BS, RFC, Dm, nullptr, nullptr);
        dim3 g2(Dm / 128, BS / 128);
        sgemm_t<1, 128><<<g2, 256>>>(t_, out_V, h_, BS, Dm, RFC, out_b, hidden);
    }

    // 6) z = LN2(h)
    ln_kernel<<<BS, 256>>>(h_, ln2_w, ln2_b, x_);

    // 7) a = gelu((z @ fc1_U) @ fc1_V + fc1_b)
    {
        dim3 g1(RFC / 64, BS / 128);
        sgemm_t<0, 64><<<g1, 256>>>(x_, fc1_U, t_, BS, RFC, Dm, nullptr, nullptr);
        dim3 g2(Ii / 128, BS / 128);
        sgemm_t<2, 128><<<g2, 256>>>(t_, fc1_V, a_, BS, Ii, RFC, fc1_b, nullptr);
    }

    // 8) out = h + (a @ fc2_U) @ fc2_V + fc2_b
    {
        dim3 g1(RFC / 64, BS / 128);
        sgemm_t<0, 64><<<g1, 256>>>(a_, fc2_U, t_, BS, RFC, Ii, nullptr, nullptr);
        dim3 g2(Dm / 128, BS / 128);
        sgemm_t<1, 128><<<g2, 256>>>(t_, fc2_V, out, BS, Dm, RFC, fc2_b, h_);
    }
}

// round 3
// speedup vs baseline: 3.6347x; 1.9239x over previous
#include <cuda_runtime.h>
#include <cuda_bf16.h>
#include <math.h>
#include <stdint.h>

// Problem dims (fixed)
#define Dm   1024
#define Hh   16
#define DH   64
#define Rr   32
#define Bb   2
#define Ss   2048
#define BS   (Bb*Ss)        // 4096
#define HR   (Hh*Rr)        // 512
#define Ii   4096
#define RFC  512

// ---------------- scratch ----------------
__device__ float g_x [BS*Dm];
__device__ float g_Pq[BS*HR];
__device__ float g_Pk[BS*HR];
__device__ float g_Pv[BS*HR];
__device__ float g_Q [Bb*Hh*Ss*DH];
__device__ float g_K [Bb*Hh*Ss*DH];
__device__ float g_V [Bb*Hh*Ss*DH];
__device__ float g_Y [BS*Dm];
__device__ float g_t [BS*RFC];
__device__ float g_h [BS*Dm];
__device__ float g_a [BS*Ii];

// ---------------- common PTX helpers ----------------
__device__ __forceinline__ void cp16(uint32_t saddr, const void* gptr) {
    asm volatile("cp.async.ca.shared.global [%0], [%1], 16;" :: "r"(saddr), "l"(gptr));
}
__device__ __forceinline__ uint32_t f2tf(float x) {
    uint32_t r;
    asm("cvt.rna.tf32.f32 %0, %1;" : "=r"(r) : "f"(x));
    return r;
}
__device__ __forceinline__ void mma_tf32(float* d, const uint32_t* a, const uint32_t* b) {
    asm volatile(
        "mma.sync.aligned.m16n8k8.row.col.f32.tf32.tf32.f32 "
        "{%0,%1,%2,%3}, {%4,%5,%6,%7}, {%8,%9}, {%0,%1,%2,%3};"
        : "+f"(d[0]), "+f"(d[1]), "+f"(d[2]), "+f"(d[3])
        : "r"(a[0]), "r"(a[1]), "r"(a[2]), "r"(a[3]), "r"(b[0]), "r"(b[1]));
}
__device__ __forceinline__ float gelu_tanh(float x) {
    float x3 = x * x * x;
    return 0.5f * x * (1.f + tanhf(0.7978845608f * (x + 0.044715f * x3)));
}

// ---------------- LayerNorm ----------------
__global__ void ln_kernel(const float* __restrict__ in, const float* __restrict__ w,
                          const float* __restrict__ b, float* __restrict__ out) {
    __shared__ float xs[Dm];
    __shared__ float red[8];
    int row = blockIdx.x;
    int t = threadIdx.x;
    const float* x = in + (size_t)row * Dm;

    float s = 0.f;
    #pragma unroll
    for (int i = t; i < Dm; i += 256) { float v = x[i]; xs[i] = v; s += v; }
    #pragma unroll
    for (int o = 16; o; o >>= 1) s += __shfl_xor_sync(0xffffffffu, s, o);
    if ((t & 31) == 0) red[t >> 5] = s;
    __syncthreads();
    float tot = 0.f;
    #pragma unroll
    for (int i = 0; i < 8; i++) tot += red[i];
    float mean = tot * (1.0f / Dm);
    __syncthreads();

    float vs = 0.f;
    #pragma unroll
    for (int i = t; i < Dm; i += 256) { float d = xs[i] - mean; vs += d * d; }
    #pragma unroll
    for (int o = 16; o; o >>= 1) vs += __shfl_xor_sync(0xffffffffu, vs, o);
    if ((t & 31) == 0) red[t >> 5] = vs;
    __syncthreads();
    float vtot = 0.f;
    #pragma unroll
    for (int i = 0; i < 8; i++) vtot += red[i];
    float rstd = rsqrtf(vtot * (1.0f / Dm) + 1e-5f);

    #pragma unroll
    for (int i = t; i < Dm; i += 256)
        out[(size_t)row * Dm + i] = (xs[i] - mean) * rstd * w[i] + b[i];
}

// ---------------- TF32 tensor-core GEMM (unchanged from R2) ----------------
template<int EPI, int BN>
__device__ __forceinline__ void gemm_core(
    const float* __restrict__ A, const float* __restrict__ B, float* __restrict__ C,
    int M, int N, int K, const float* __restrict__ bias, const float* __restrict__ res,
    int m0, int n0)
{
    constexpr int BM = 128, BK = 16;
    constexpr int WM_ = (BN == 128) ? 2 : 4;
    constexpr int WTM = BM / WM_;
    constexpr int WTN = BN / (8 / WM_);
    constexpr int MT = WTM / 16;
    constexpr int NT = WTN / 8;

    __shared__ __align__(16) float As[2][BM][BK + 4];
    __shared__ __align__(16) float Bs[2][BK][BN + 8];

    int tid = threadIdx.x;
    int w = tid >> 5, lane = tid & 31;
    int lr = lane >> 2, lc = lane & 3;
    int wm = (w % WM_) * WTM;
    int wn = (w / WM_) * WTN;

    float acc[MT][NT][4];
    #pragma unroll
    for (int mt = 0; mt < MT; mt++)
        #pragma unroll
        for (int nt = 0; nt < NT; nt++)
            #pragma unroll
            for (int i = 0; i < 4; i++) acc[mt][nt][i] = 0.f;

    const float* Ag = A + (size_t)m0 * K;
    const float* Bg = B + n0;

    auto loadTile = [&](int kt, int buf) {
        int k0 = kt * BK;
        #pragma unroll
        for (int i = 0; i < 2; i++) {
            int q = tid * 2 + i;
            int m = q >> 2, c = q & 3;
            uint32_t s = (uint32_t)__cvta_generic_to_shared(&As[buf][m][c * 4]);
            cp16(s, Ag + (size_t)m * K + k0 + c * 4);
        }
        #pragma unroll
        for (int i = 0; i < BN / 64; i++) {
            int q = tid + i * 256;
            int k = q / (BN / 4), n4 = q % (BN / 4);
            uint32_t s = (uint32_t)__cvta_generic_to_shared(&Bs[buf][k][n4 * 4]);
            cp16(s, Bg + (size_t)(k0 + k) * N + n4 * 4);
        }
        asm volatile("cp.async.commit_group;");
    };

    int NTILES = K / BK;
    loadTile(0, 0);
    for (int kt = 0; kt < NTILES; kt++) {
        int buf = kt & 1;
        if (kt + 1 < NTILES) {
            loadTile(kt + 1, buf ^ 1);
            asm volatile("cp.async.wait_group 1;");
        } else {
            asm volatile("cp.async.wait_group 0;");
        }
        __syncthreads();

        #pragma unroll
        for (int ks = 0; ks < 2; ks++) {
            int kb = ks * 8;
            uint32_t af[MT][4], bf[NT][2];
            #pragma unroll
            for (int mt = 0; mt < MT; mt++) {
                int r = wm + mt * 16 + lr;
                af[mt][0] = f2tf(As[buf][r][kb + lc]);
                af[mt][1] = f2tf(As[buf][r + 8][kb + lc]);
                af[mt][2] = f2tf(As[buf][r][kb + lc + 4]);
                af[mt][3] = f2tf(As[buf][r + 8][kb + lc + 4]);
            }
            #pragma unroll
            for (int nt = 0; nt < NT; nt++) {
                int cn = wn + nt * 8 + lr;
                bf[nt][0] = f2tf(Bs[buf][kb + lc][cn]);
                bf[nt][1] = f2tf(Bs[buf][kb + lc + 4][cn]);
            }
            #pragma unroll
            for (int mt = 0; mt < MT; mt++)
                #pragma unroll
                for (int nt = 0; nt < NT; nt++)
                    mma_tf32(acc[mt][nt], af[mt], bf[nt]);
        }
        __syncthreads();
    }

    #pragma unroll
    for (int mt = 0; mt < MT; mt++) {
        #pragma unroll
        for (int h = 0; h < 2; h++) {
            int row = m0 + wm + mt * 16 + lr + h * 8;
            #pragma unroll
            for (int nt = 0; nt < NT; nt++) {
                int col = n0 + wn + nt * 8 + 2 * lc;
                float v0 = acc[mt][nt][2 * h + 0];
                float v1 = acc[mt][nt][2 * h + 1];
                if (EPI == 1) {
                    v0 += bias[col]     + res[(size_t)row * N + col];
                    v1 += bias[col + 1] + res[(size_t)row * N + col + 1];
                } else if (EPI == 2) {
                    v0 = gelu_tanh(v0 + bias[col]);
                    v1 = gelu_tanh(v1 + bias[col + 1]);
                }
                *(float2*)&C[(size_t)row * N + col] = make_float2(v0, v1);
            }
        }
    }
}

template<int EPI, int BN>
__global__ void __launch_bounds__(256, 2) sgemm_t(
    const float* __restrict__ A, const float* __restrict__ B, float* __restrict__ C,
    int M, int N, int K, const float* __restrict__ bias, const float* __restrict__ res)
{
    gemm_core<EPI, BN>(A, B, C, M, N, K, bias, res, blockIdx.y * 128, blockIdx.x * BN);
}

__global__ void __launch_bounds__(256, 2) sgemm_qkv(
    const float* __restrict__ A,
    const float* __restrict__ B0, const float* __restrict__ B1, const float* __restrict__ B2,
    float* __restrict__ C0, float* __restrict__ C1, float* __restrict__ C2,
    int M, int N, int K)
{
    int sel = blockIdx.x >> 2, nb = blockIdx.x & 3;
    const float* B = (sel == 0) ? B0 : (sel == 1) ? B1 : B2;
    float* C = (sel == 0) ? C0 : (sel == 1) ? C1 : C2;
    gemm_core<0, 128>(A, B, C, M, N, K, nullptr, nullptr, blockIdx.y * 128, nb * 128);
}

// ---------------- head_proj v2: fused q/k/v, smem-cached weights ----------------
__global__ void __launch_bounds__(256) head_proj2(
    const float* __restrict__ Pq, const float* __restrict__ Pk, const float* __restrict__ Pv,
    const float* __restrict__ Vq, const float* __restrict__ Vk, const float* __restrict__ Vv,
    const float* __restrict__ bq, const float* __restrict__ bk, const float* __restrict__ bv,
    float* __restrict__ Oq, float* __restrict__ Ok, float* __restrict__ Ov)
{
    __shared__ float vw[Rr][DH];
    __shared__ float pt[64][Rr + 1];
    int z = blockIdx.z;
    const float* P  = (z == 0) ? Pq : (z == 1) ? Pk : Pv;
    const float* Vw = (z == 0) ? Vq : (z == 1) ? Vk : Vv;
    const float* bi = (z == 0) ? bq : (z == 1) ? bk : bv;
    float* O        = (z == 0) ? Oq : (z == 1) ? Ok : Ov;

    int h = blockIdx.y;
    int s0 = blockIdx.x * 64;
    int tid = threadIdx.x;

    #pragma unroll
    for (int i = 0; i < 8; i++) {                // Vw[h]: 32x64
        int idx = tid + i * 256;
        vw[idx >> 6][idx & 63] = Vw[(size_t)h * Rr * DH + idx];
    }
    #pragma unroll
    for (int i = 0; i < 8; i++) {                // P tile: 64 rows x 32
        int idx = tid + i * 256;
        int r = idx >> 5, c = idx & 31;
        pt[r][c] = P[(size_t)(s0 + r) * HR + h * Rr + c];
    }
    __syncthreads();

    int e = tid & 63;
    int sl = tid >> 6;                           // 0..3
    float bv_ = bi[h * DH + e];
    #pragma unroll
    for (int i = 0; i < 16; i++) {
        int r = sl + i * 4;
        float acc = bv_;
        #pragma unroll
        for (int rr = 0; rr < Rr; rr++) acc = fmaf(pt[r][rr], vw[rr][e], acc);
        int bs = s0 + r;
        int b = bs >> 11, s = bs & 2047;
        O[(((size_t)(b * Hh + h)) * Ss + s) * DH + e] = acc;
    }
}

// ---------------- TF32 tensor-core causal flash attention ----------------
// 64 queries/block, 4 warps (16 rows each), 64-key tiles.
__global__ void __launch_bounds__(128) attn_mma(
    const float* __restrict__ Q, const float* __restrict__ K,
    const float* __restrict__ V, float* __restrict__ Y)
{
    __shared__ uint32_t Ks[64][68];   // K tile (tf32 bits); reused for P
    __shared__ uint32_t Vs[64][72];   // V tile (tf32 bits)

    int bh = blockIdx.y;
    int qblk = gridDim.x - 1 - blockIdx.x;       // heavy blocks first
    int tid = threadIdx.x;
    int w = tid >> 5, lane = tid & 31;
    int lr = lane >> 2, lc = lane & 3;
    int q0 = qblk * 64;
    int wq = w * 16;

    // Q fragments, persistent in registers (rows wq+lr, wq+lr+8)
    uint32_t qf[8][4];
    const float* Qb = Q + ((size_t)bh * Ss + q0 + wq) * DH;
    #pragma unroll
    for (int ks = 0; ks < 8; ks++) {
        qf[ks][0] = f2tf(Qb[(size_t)lr * DH + ks * 8 + lc]);
        qf[ks][1] = f2tf(Qb[(size_t)(lr + 8) * DH + ks * 8 + lc]);
        qf[ks][2] = f2tf(Qb[(size_t)lr * DH + ks * 8 + lc + 4]);
        qf[ks][3] = f2tf(Qb[(size_t)(lr + 8) * DH + ks * 8 + lc + 4]);
    }

    float o[8][4];
    #pragma unroll
    for (int nt = 0; nt < 8; nt++)
        #pragma unroll
        for (int i = 0; i < 4; i++) o[nt][i] = 0.f;
    float m0 = -1e30f, m1 = -1e30f, l0 = 0.f, l1 = 0.f;
    const float scale = 0.125f;

    for (int kt = 0; kt <= qblk; kt++) {
        const float* kb_ = K + ((size_t)bh * Ss + kt * 64) * DH;
        const float* vb_ = V + ((size_t)bh * Ss + kt * 64) * DH;
        __syncthreads();                          // prior tile's P/V reads done
        #pragma unroll
        for (int i = 0; i < 8; i++) {             // stage K,V with tf32 cvt
            int idx = tid + i * 128;              // 0..1023
            int r = idx >> 4, c4 = (idx & 15) * 4;
            float4 kv = *(const float4*)(kb_ + (size_t)r * DH + c4);
            Ks[r][c4 + 0] = f2tf(kv.x); Ks[r][c4 + 1] = f2tf(kv.y);
            Ks[r][c4 + 2] = f2tf(kv.z); Ks[r][c4 + 3] = f2tf(kv.w);
            float4 vv = *(const float4*)(vb_ + (size_t)r * DH + c4);
            Vs[r][c4 + 0] = f2tf(vv.x); Vs[r][c4 + 1] = f2tf(vv.y);
            Vs[r][c4 + 2] = f2tf(vv.z); Vs[r][c4 + 3] = f2tf(vv.w);
        }
        __syncthreads();

        // S = Q @ K^T   (per warp: 16 x 64)
        float s[8][4];
        #pragma unroll
        for (int nt = 0; nt < 8; nt++)
            #pragma unroll
            for (int i = 0; i < 4; i++) s[nt][i] = 0.f;
        #pragma unroll
        for (int ks = 0; ks < 8; ks++) {
            #pragma unroll
            for (int nt = 0; nt < 8; nt++) {
                uint32_t bf[2];
                bf[0] = Ks[nt * 8 + lr][ks * 8 + lc];
                bf[1] = Ks[nt * 8 + lr][ks * 8 + lc + 4];
                mma_tf32(s[nt], qf[ks], bf);
            }
        }

        // scale + causal mask (diagonal tile only)
        bool diag = (kt == qblk);
        int r0 = wq + lr, r1 = wq + lr + 8;
        #pragma unroll
        for (int nt = 0; nt < 8; nt++) {
            int c0 = nt * 8 + 2 * lc, c1 = c0 + 1;
            s[nt][0] = (diag && c0 > r0) ? -1e30f : s[nt][0] * scale;
            s[nt][1] = (diag && c1 > r0) ? -1e30f : s[nt][1] * scale;
            s[nt][2] = (diag && c0 > r1) ? -1e30f : s[nt][2] * scale;
            s[nt][3] = (diag && c1 > r1) ? -1e30f : s[nt][3] * scale;
        }

        // row max (quad reduce)
        float mx0 = -1e30f, mx1 = -1e30f;
        #pragma unroll
        for (int nt = 0; nt < 8; nt++) {
            mx0 = fmaxf(mx0, fmaxf(s[nt][0], s[nt][1]));
            mx1 = fmaxf(mx1, fmaxf(s[nt][2], s[nt][3]));
        }
        mx0 = fmaxf(mx0, __shfl_xor_sync(0xffffffffu, mx0, 1));
        mx0 = fmaxf(mx0, __shfl_xor_sync(0xffffffffu, mx0, 2));
        mx1 = fmaxf(mx1, __shfl_xor_sync(0xffffffffu, mx1, 1));
        mx1 = fmaxf(mx1, __shfl_xor_sync(0xffffffffu, mx1, 2));
        float mn0 = fmaxf(m0, mx0), mn1 = fmaxf(m1, mx1);
        float c0f = __expf(m0 - mn0), c1f = __expf(m1 - mn1);
        l0 *= c0f; l1 *= c1f;
        #pragma unroll
        for (int nt = 0; nt < 8; nt++) {
            o[nt][0] *= c0f; o[nt][1] *= c0f;
            o[nt][2] *= c1f; o[nt][3] *= c1f;
        }
        m0 = mn0; m1 = mn1;

        __syncthreads();                          // all warps done reading Ks
        // P = exp(s - m), write to Ks (reused as P buffer)
        #pragma unroll
        for (int nt = 0; nt < 8; nt++) {
            int c0 = nt * 8 + 2 * lc;
            float p00 = __expf(s[nt][0] - mn0);
            float p01 = __expf(s[nt][1] - mn0);
            float p10 = __expf(s[nt][2] - mn1);
            float p11 = __expf(s[nt][3] - mn1);
            l0 += p00 + p01; l1 += p10 + p11;
            Ks[wq + lr][c0] = f2tf(p00);     Ks[wq + lr][c0 + 1] = f2tf(p01);
            Ks[wq + lr + 8][c0] = f2tf(p10); Ks[wq + lr + 8][c0 + 1] = f2tf(p11);
        }
        __syncthreads();

        // O += P @ V
        #pragma unroll
        for (int ks = 0; ks < 8; ks++) {
            uint32_t pa[4];
            pa[0] = Ks[wq + lr][ks * 8 + lc];
            pa[1] = Ks[wq + lr + 8][ks * 8 + lc];
            pa[2] = Ks[wq + lr][ks * 8 + lc + 4];
            pa[3] = Ks[wq + lr + 8][ks * 8 + lc + 4];
            #pragma unroll
            for (int nt = 0; nt < 8; nt++) {
                uint32_t bf[2];
                bf[0] = Vs[ks * 8 + lc][nt * 8 + lr];
                bf[1] = Vs[ks * 8 + lc + 4][nt * 8 + lr];
                mma_tf32(o[nt], pa, bf);
            }
        }
    }

    // epilogue: reduce l across quad, normalize, store (b,s,h,e)
    l0 += __shfl_xor_sync(0xffffffffu, l0, 1);
    l0 += __shfl_xor_sync(0xffffffffu, l0, 2);
    l1 += __shfl_xor_sync(0xffffffffu, l1, 1);
    l1 += __shfl_xor_sync(0xffffffffu, l1, 2);
    float i0 = 1.f / l0, i1 = 1.f / l1;
    int b = bh >> 4, h = bh & 15;
    int row0 = q0 + wq + lr, row1 = row0 + 8;
    float* y0 = Y + (((size_t)(b * Ss + row0)) * Hh + h) * DH;
    float* y1 = Y + (((size_t)(b * Ss + row1)) * Hh + h) * DH;
    #pragma unroll
    for (int nt = 0; nt < 8; nt++) {
        int c = nt * 8 + 2 * lc;
        *(float2*)(y0 + c) = make_float2(o[nt][0] * i0, o[nt][1] * i0);
        *(float2*)(y1 + c) = make_float2(o[nt][2] * i1, o[nt][3] * i1);
    }
}

// ---------------- launch ----------------
extern "C" void kernel_launch(void* const* d_in, const int* in_sizes, int n_in,
                              void* d_out, int out_size) {
    const float* hidden = (const float*)d_in[0];
    const float* ln1_w = (const float*)d_in[2];
    const float* ln1_b = (const float*)d_in[3];
    const float* q_U = (const float*)d_in[4];
    const float* q_V = (const float*)d_in[5];
    const float* q_b = (const float*)d_in[6];
    const float* k_U = (const float*)d_in[7];
    const float* k_V = (const float*)d_in[8];
    const float* k_b = (const float*)d_in[9];
    const float* v_U = (const float*)d_in[10];
    const float* v_V = (const float*)d_in[11];
    const float* v_b = (const float*)d_in[12];
    const float* out_U = (const float*)d_in[13];
    const float* out_V = (const float*)d_in[14];
    const float* out_b = (const float*)d_in[15];
    const float* ln2_w = (const float*)d_in[16];
    const float* ln2_b = (const float*)d_in[17];
    const float* fc1_U = (const float*)d_in[18];
    const float* fc1_V = (const float*)d_in[19];
    const float* fc1_b = (const float*)d_in[20];
    const float* fc2_U = (const float*)d_in[21];
    const float* fc2_V = (const float*)d_in[22];
    const float* fc2_b = (const float*)d_in[23];
    float* out = (float*)d_out;

    float *x_, *Pq_, *Pk_, *Pv_, *Q_, *K_, *V_, *Y_, *t_, *h_, *a_;
    cudaGetSymbolAddress((void**)&x_,  g_x);
    cudaGetSymbolAddress((void**)&Pq_, g_Pq);
    cudaGetSymbolAddress((void**)&Pk_, g_Pk);
    cudaGetSymbolAddress((void**)&Pv_, g_Pv);
    cudaGetSymbolAddress((void**)&Q_,  g_Q);
    cudaGetSymbolAddress((void**)&K_,  g_K);
    cudaGetSymbolAddress((void**)&V_,  g_V);
    cudaGetSymbolAddress((void**)&Y_,  g_Y);
    cudaGetSymbolAddress((void**)&t_,  g_t);
    cudaGetSymbolAddress((void**)&h_,  g_h);
    cudaGetSymbolAddress((void**)&a_,  g_a);

    // 1) x = LN1(hidden)
    ln_kernel<<<BS, 256>>>(hidden, ln1_w, ln1_b, x_);

    // 2) Pq/Pk/Pv = x @ {q,k,v}_U  (fused launch)
    {
        dim3 g(12, BS / 128);
        sgemm_qkv<<<g, 256>>>(x_, q_U, k_U, v_U, Pq_, Pk_, Pv_, BS, HR, Dm);
    }

    // 3) head expansion (fused q/k/v)
    {
        dim3 g(BS / 64, Hh, 3);
        head_proj2<<<g, 256>>>(Pq_, Pk_, Pv_, q_V, k_V, v_V, q_b, k_b, v_b, Q_, K_, V_);
    }

    // 4) causal attention -> Y (b,s,h,e)
    {
        dim3 g(Ss / 64, Bb * Hh);
        attn_mma<<<g, 128>>>(Q_, K_, V_, Y_);
    }

    // 5) h = hidden + (Y @ out_U) @ out_V + out_b
    {
        dim3 g1(RFC / 64, BS / 128);
        sgemm_t<0, 64><<<g1, 256>>>(Y_, out_U, t_, BS, RFC, Dm, nullptr, nullptr);
        dim3 g2(Dm / 128, BS / 128);
        sgemm_t<1, 128><<<g2, 256>>>(t_, out_V, h_, BS, Dm, RFC, out_b, hidden);
    }

    // 6) z = LN2(h)
    ln_kernel<<<BS, 256>>>(h_, ln2_w, ln2_b, x_);

    // 7) a = gelu((z @ fc1_U) @ fc1_V + fc1_b)
    {
        dim3 g1(RFC / 64, BS / 128);
        sgemm_t<0, 64><<<g1, 256>>>(x_, fc1_U, t_, BS, RFC, Dm, nullptr, nullptr);
        dim3 g2(Ii / 128, BS / 128);
        sgemm_t<2, 128><<<g2, 256>>>(t_, fc1_V, a_, BS, Ii, RFC, fc1_b, nullptr);
    }

    // 8) out = h + (a @ fc2_U) @ fc2_V + fc2_b
    {
        dim3 g1(RFC / 64, BS / 128);
        sgemm_t<0, 64><<<g1, 256>>>(a_, fc2_U, t_, BS, RFC, Ii, nullptr, nullptr);
        dim3 g2(Dm / 128, BS / 128);
        sgemm_t<1, 128><<<g2, 256>>>(t_, fc2_V, out, BS, Dm, RFC, fc2_b, h_);
    }
}